// round 1
// baseline (speedup 1.0000x reference)
#include <cuda_runtime.h>
#include <math.h>

// ---------------- problem constants ----------------
#define NB   32
#define NC   8
#define TLEN 512
#define NSH  5
#define XROW 520          // padded x row (max over-read index is 519)
#define TT   8            // m-windows per thread (rolling register window)
#define NCOL 160          // 4 sets * 5 * 8
#define NOUT 10

// d_out layout (flattened reference outputs, in order):
//   [0,320)        out        (32,10)
//   [320,5440)     dists      (32,160)
//   [5440,10560)   probs      (32,160)
//   [10560]        loss
#define OFF_DIST 320
#define OFF_PROB 5440
#define OFF_LOSS 10560

// ---------------- device scratch (static, allowed) ----------------
__device__ float    g_xn[NB * NC * XROW];
__device__ unsigned g_denc[NB * NCOL];
__device__ unsigned g_pbits[NB * NCOL];

// order-preserving float<->uint encodings (for atomic min / max)
__device__ __forceinline__ unsigned fenc(float f) {
    unsigned u = __float_as_uint(f);
    return (u & 0x80000000u) ? ~u : (u | 0x80000000u);
}
__device__ __forceinline__ float fdec(unsigned e) {
    unsigned u = (e & 0x80000000u) ? (e & 0x7fffffffu) : ~e;
    return __uint_as_float(u);
}

// ---------------- init scratch ----------------
__global__ void k_init() {
    int i = blockIdx.x * blockDim.x + threadIdx.x;
    if (i < NB * NCOL) { g_denc[i] = 0xFFFFFFFFu; g_pbits[i] = 0u; }
}

// ---------------- per-(b,c) normalization: mean / std(ddof=1) ----------------
__global__ void k_norm(const float* __restrict__ x) {
    int bc = blockIdx.x;                 // b*8 + c
    const float* row = x + bc * TLEN;
    float* orow = g_xn + bc * XROW;
    int tid = threadIdx.x;               // 128 threads
    float v[4];
    float s = 0.f;
#pragma unroll
    for (int k = 0; k < 4; k++) { v[k] = row[tid + 128 * k]; s += v[k]; }
    __shared__ float red[128];
    red[tid] = s; __syncthreads();
    for (int off = 64; off; off >>= 1) { if (tid < off) red[tid] += red[tid + off]; __syncthreads(); }
    float mu = red[0] / 512.f;
    __syncthreads();
    float q = 0.f;
#pragma unroll
    for (int k = 0; k < 4; k++) { float d = v[k] - mu; q += d * d; }
    red[tid] = q; __syncthreads();
    for (int off = 64; off; off >>= 1) { if (tid < off) red[tid] += red[tid + off]; __syncthreads(); }
    float sd = sqrtf(red[0] / 511.f);
    float sc = 1.f / (sd + 1e-8f);
#pragma unroll
    for (int k = 0; k < 4; k++) orow[tid + 128 * k] = (v[k] - mu) * sc;
    if (tid < XROW - TLEN) orow[TLEN + tid] = 0.f;   // zero the pad
}

// ---------------- main shapelet distance kernel ----------------
// grid = NB * 14 blocks; block bx -> (b, slot); slot -> (set, m-chunk)
__global__ void k_main(const float* __restrict__ w0, const float* __restrict__ w1,
                       const float* __restrict__ w2, const float* __restrict__ w3,
                       const float* __restrict__ p0, const float* __restrict__ p1,
                       const float* __restrict__ p2, const float* __restrict__ p3) {
    const int Ls[4]  = {52, 103, 154, 256};
    const int Ms[4]  = {461, 410, 359, 257};
    const int LP[4]  = {53, 103, 155, 257};   // odd-padded w rows (bank spread)
    const int NTt[4] = {58, 52, 45, 33};      // ceil(m/TT)
    const int CHb[4] = {0, 2, 5, 9};          // slot base per set
    const int CHn[4] = {2, 3, 4, 5};          // chunks per set (load balance)
    const signed char SLOT_SET[14] = {0,0,1,1,1,2,2,2,2,3,3,3,3,3};

    int bx = blockIdx.x;
    int b = bx / 14, slot = bx % 14;
    int s = SLOT_SET[slot];
    int q = slot - CHb[s];
    int NT = NTt[s];
    int t0 = (NT * q) / CHn[s];
    int t1 = (NT * (q + 1)) / CHn[s];
    int l = Ls[s], m = Ms[s], lpad = LP[s];
    const float* wp = (s == 0) ? w0 : (s == 1) ? w1 : (s == 2) ? w2 : w3;
    const float* pp = (s == 0) ? p0 : (s == 1) ? p1 : (s == 2) ? p2 : p3;

    extern __shared__ float sm[];
    float* sx = sm;                 // NC * XROW
    float* sw = sm + NC * XROW;     // (NSH*NC) * lpad

    int tid = threadIdx.x, bs = blockDim.x;
    for (int i = tid; i < NC * XROW; i += bs) sx[i] = g_xn[b * NC * XROW + i];
    int wtot = NSH * NC * l;
    for (int i = tid; i < wtot; i += bs) {
        int r = i / l, j = i - r * l;
        sw[r * lpad + j] = wp[i];
    }
    __syncthreads();

    int ntc = t1 - t0;
    int items = NSH * NC * ntc;     // nc fastest -> warp lanes spread over (n,c)
    for (int it = tid; it < items; it += bs) {
        int tl = it / (NSH * NC);
        int nc = it - tl * (NSH * NC);       // n*8 + c
        int m0 = (t0 + tl) * TT;
        int c = nc & 7;
        const float* xr = sx + c * XROW + m0;
        const float* wr = sw + nc * lpad;

        float acc[TT], xv[TT];
#pragma unroll
        for (int t = 0; t < TT; t++) { acc[t] = 0.f; xv[t] = xr[t]; }
#pragma unroll 4
        for (int j = 0; j < l; j++) {
            float wj = wr[j];
#pragma unroll
            for (int t = 0; t < TT; t++) acc[t] += fabsf(xv[t] - wj);
#pragma unroll
            for (int t = 0; t < TT - 1; t++) xv[t] = xv[t + 1];
            xv[TT - 1] = xr[j + TT];
        }

        float invl = 1.f / (float)l;
        float dmin = 3.4e38f, damin = 3.4e38f;
        const float* pr = pp + c * m;        // pcm is (c, m)
#pragma unroll
        for (int t = 0; t < TT; t++) {
            int mm = m0 + t;
            if (mm < m) {
                float d = acc[t] * invl * pr[mm];
                dmin = fminf(dmin, d);
                damin = fminf(damin, fabsf(d));
            }
        }
        float p = expf(-damin * damin);      // = max_m exp(-d^2)
        int idx = b * NCOL + s * 40 + nc;
        atomicMin(&g_denc[idx], fenc(dmin));
        atomicMax(&g_pbits[idx], __float_as_uint(p));
    }
}

// ---------------- decode scratch -> dists / probs ----------------
__global__ void k_decode(float* __restrict__ out) {
    int i = blockIdx.x * blockDim.x + threadIdx.x;
    if (i < NB * NCOL) {
        out[OFF_DIST + i] = fdec(g_denc[i]);
        out[OFF_PROB + i] = __uint_as_float(g_pbits[i]);
    }
}

// ---------------- matmul + losses ----------------
__global__ void k_final(float* __restrict__ out, const float* __restrict__ Wout,
                        const float* __restrict__ w0, const float* __restrict__ w1,
                        const float* __restrict__ w2, const float* __restrict__ w3) {
    int tid = threadIdx.x;   // 320 threads
    if (blockIdx.x == 0) {
        if (tid < NB * NOUT) {
            int bb = tid / NOUT, o = tid - bb * NOUT;
            const float* prw = out + OFF_PROB + bb * NCOL;
            const float* wr = Wout + o * NCOL;
            float sacc = 0.f;
#pragma unroll 8
            for (int j = 0; j < NCOL; j++) sacc += prw[j] * wr[j];
            out[bb * NOUT + o] = sacc;
        }
    } else {
        // reg loss
        float reg = 0.f;
        for (int i = tid; i < NOUT * NCOL; i += 320) reg += fabsf(Wout[i]);
        // diversity loss
        const int Ls[4] = {52, 103, 154, 256};
        const float* wps[4] = {w0, w1, w2, w3};
        float div = 0.f;
        for (int t = tid; t < 800; t += 320) {
            int s = t / 200; int r = t % 200;
            int c = r / 25; int ij = r % 25; int i = ij / 5, j = ij % 5;
            if (i == j) continue;
            int l = Ls[s];
            const float* wa = wps[s] + (i * 8 + c) * l;
            const float* wb = wps[s] + (j * 8 + c) * l;
            float ss = 0.f;
            for (int kk = 0; kk < l; kk++) { float d = wa[kk] - wb[kk] + 1e-6f; ss += d * d; }
            div += expf(-sqrtf(ss)) * (1.f / 200.f);
        }
        __shared__ float r1[512], r2[512];
        r1[tid] = reg; r2[tid] = div;
        if (tid < 192) { r1[tid + 320] = 0.f; r2[tid + 320] = 0.f; }
        __syncthreads();
        for (int off = 256; off; off >>= 1) {
            if (tid < off) { r1[tid] += r1[tid + off]; r2[tid] += r2[tid + off]; }
            __syncthreads();
        }
        if (tid == 0) out[OFF_LOSS] = 0.1f * (r1[0] / 1600.f) + 0.1f * r2[0];
    }
}

// ---------------- launch ----------------
extern "C" void kernel_launch(void* const* d_in, const int* in_sizes, int n_in,
                              void* d_out, int out_size) {
    const float* x = nullptr;
    const float* w[4] = {nullptr, nullptr, nullptr, nullptr};
    const float* pcm[4] = {nullptr, nullptr, nullptr, nullptr};
    const float* Wout = nullptr;
    for (int i = 0; i < n_in; i++) {
        switch (in_sizes[i]) {
            case 131072: x = (const float*)d_in[i]; break;
            case 2080:  w[0] = (const float*)d_in[i]; break;
            case 4120:  w[1] = (const float*)d_in[i]; break;
            case 6160:  w[2] = (const float*)d_in[i]; break;
            case 10240: w[3] = (const float*)d_in[i]; break;
            case 3688:  pcm[0] = (const float*)d_in[i]; break;
            case 3280:  pcm[1] = (const float*)d_in[i]; break;
            case 2872:  pcm[2] = (const float*)d_in[i]; break;
            case 2056:  pcm[3] = (const float*)d_in[i]; break;
            case 1600:  Wout = (const float*)d_in[i]; break;
            default: break;
        }
    }
    float* out = (float*)d_out;

    static int smem_set = 0;
    int smem_bytes = (NC * XROW + NSH * NC * 257) * 4;  // 57760
    if (!smem_set) {
        cudaFuncSetAttribute(k_main, cudaFuncAttributeMaxDynamicSharedMemorySize, smem_bytes);
        smem_set = 1;
    }

    k_init<<<20, 256>>>();
    k_norm<<<NB * NC, 128>>>(x);
    k_main<<<NB * 14, 256, smem_bytes>>>(w[0], w[1], w[2], w[3],
                                         pcm[0], pcm[1], pcm[2], pcm[3]);
    k_decode<<<20, 256>>>(out);
    k_final<<<2, 320>>>(out, Wout, w[0], w[1], w[2], w[3]);
    (void)out_size;
}

// round 2
// speedup vs baseline: 1.0512x; 1.0512x over previous
#include <cuda_runtime.h>
#include <math.h>

// ---------------- problem constants ----------------
#define NB   32
#define NC   8
#define TLEN 512
#define NSH  5
#define GXROW 544         // padded g_xn row (zeros 512..543)
#define NCOL 160
#define NOUT 10

#define OFF_DIST 320
#define OFF_PROB 5440
#define OFF_LOSS 10560

// smem layout (words)
#define SXSTR  546                 // x row stride, ≡2 mod 32 -> conflict-free LDS.64
#define SX1OFF (8*546)             // shifted copy
#define SWOFF  (2*8*546)           // negated-w region
#define WWMAX  258
#define SRED_OFF (SWOFF + 40*WWMAX)
#define SM_WORDS (SRED_OFF + 80)
#define SM_BYTES (SM_WORDS*4)      // 76864 B

typedef unsigned long long ull;

__device__ float    g_xn[NB*NC*GXROW];
__device__ unsigned g_denc[NB*NCOL];
__device__ unsigned g_pbits[NB*NCOL];

__device__ __forceinline__ unsigned fenc(float f){unsigned u=__float_as_uint(f);return (u&0x80000000u)?~u:(u|0x80000000u);}
__device__ __forceinline__ float fdec(unsigned e){unsigned u=(e&0x80000000u)?(e&0x7fffffffu):~e;return __uint_as_float(u);}

__device__ __forceinline__ ull addf2(ull a, ull b){
    ull r; asm("add.rn.f32x2 %0, %1, %2;" : "=l"(r) : "l"(a), "l"(b)); return r;
}
__device__ __forceinline__ float lo32(ull v){ return __uint_as_float((unsigned)(v & 0xffffffffull)); }
__device__ __forceinline__ float hi32(ull v){ return __uint_as_float((unsigned)(v >> 32)); }

// ---------------- norm (+ scratch init) ----------------
__global__ void k_norm(const float* __restrict__ x) {
    int bc = blockIdx.x;                 // b*8 + c
    const float* row = x + bc * TLEN;
    float* orow = g_xn + bc * GXROW;
    int tid = threadIdx.x;               // 128
    float v[4]; float s = 0.f;
#pragma unroll
    for (int k = 0; k < 4; k++) { v[k] = row[tid + 128*k]; s += v[k]; }
    __shared__ float red[128];
    red[tid] = s; __syncthreads();
    for (int off = 64; off; off >>= 1) { if (tid < off) red[tid] += red[tid+off]; __syncthreads(); }
    float mu = red[0] / 512.f;
    __syncthreads();
    float q = 0.f;
#pragma unroll
    for (int k = 0; k < 4; k++) { float d = v[k]-mu; q += d*d; }
    red[tid] = q; __syncthreads();
    for (int off = 64; off; off >>= 1) { if (tid < off) red[tid] += red[tid+off]; __syncthreads(); }
    float sc = 1.f / (sqrtf(red[0]/511.f) + 1e-8f);
#pragma unroll
    for (int k = 0; k < 4; k++) orow[tid + 128*k] = (v[k]-mu)*sc;
    if (tid < 32) orow[512 + tid] = 0.f;
    int gid = bc*128 + tid;
    if (gid < NB*NCOL) { g_denc[gid] = 0xFFFFFFFFu; g_pbits[gid] = 0u; }
}

// ---------------- packed shapelet core ----------------
template<int L, int M, int WW>
__device__ __forceinline__ void proc(const float* __restrict__ sx, const float* __restrict__ sw,
                                     const float* __restrict__ pcm,
                                     unsigned* sden, unsigned* spb,
                                     int t0, int t1, int tid, int bs)
{
    constexpr int NP  = L/2;
    constexpr int REM = NP % 8;
    constexpr int MAIN = NP - REM;
    constexpr bool ODD = (L & 1);
    constexpr float INVL = 1.0f/(float)L;

    int items = (t1 - t0) * 80;
    for (int it = tid; it < items; it += bs) {
        int nc = it % 40;
        int r  = it / 40;
        int P  = r & 1;
        int tl = t0 + (r >> 1);
        int c  = nc & 7;
        const float* xr = sx + P*SX1OFF + c*SXSTR + 16*tl;
        const float* wr = sw + nc*WW;

        ull xq[8], acc[8];
#pragma unroll
        for (int k = 0; k < 8; k++) { xq[k] = *(const ull*)(xr + 2*k); acc[k] = 0ull; }

        for (int st = 0; st < MAIN; st += 8) {
#pragma unroll
            for (int u = 0; u < 8; u++) {
                ull wp = *(const ull*)(wr + 2*(st+u));
#pragma unroll
                for (int k = 0; k < 8; k++) {
                    ull d = addf2(xq[(k+u)&7], wp);      // x + (-w)
                    d &= 0x7FFFFFFF7FFFFFFFull;          // packed abs
                    acc[k] = addf2(acc[k], d);
                }
                xq[u] = *(const ull*)(xr + 2*(st+u) + 16);
            }
        }
#pragma unroll
        for (int u = 0; u < REM; u++) {
            ull wp = *(const ull*)(wr + 2*(MAIN+u));
#pragma unroll
            for (int k = 0; k < 8; k++) {
                ull d = addf2(xq[(k+u)&7], wp);
                d &= 0x7FFFFFFF7FFFFFFFull;
                acc[k] = addf2(acc[k], d);
            }
            xq[u&7] = *(const ull*)(xr + 2*(MAIN+u) + 16);
        }

        float dmin = 3.4e38f, qmin = 3.4e38f;
        const float* pr = pcm + c*M;
#pragma unroll
        for (int k = 0; k < 8; k++) {
            int mm = 16*tl + 2*k + P;
            if (mm < M) {
                float ssum = lo32(acc[k]) + hi32(acc[k]);
                if (ODD) {
                    // phase after loops is REM; xq[(k+REM)&7].lo = x[W_k + L-1]
                    float xv = lo32(xq[(k+REM)&7]);
                    ssum += fabsf(xv + wr[L-1]);         // wr holds -w
                }
                float d = ssum * INVL * pr[mm];
                dmin = fminf(dmin, d);
                qmin = fminf(qmin, fabsf(d));
            }
        }
        float p = expf(-qmin*qmin);
        atomicMin(&sden[nc], fenc(dmin));
        atomicMax(&spb[nc], __float_as_uint(p));
    }
}

// grid = NB*14; block 256
__global__ void k_main(const float* __restrict__ w0, const float* __restrict__ w1,
                       const float* __restrict__ w2, const float* __restrict__ w3,
                       const float* __restrict__ p0, const float* __restrict__ p1,
                       const float* __restrict__ p2, const float* __restrict__ p3) {
    const int Ls[4]   = {52, 103, 154, 256};
    const int NT16[4] = {29, 26, 23, 17};
    const int CHb[4]  = {0, 2, 5, 9};
    const int CHn[4]  = {2, 3, 4, 5};
    const int WWs[4]  = {66, 130, 162, 258};
    const signed char SLOT_SET[14] = {0,0,1,1,1,2,2,2,2,3,3,3,3,3};

    int bx = blockIdx.x;
    int b = bx / 14, slot = bx % 14;
    int s = SLOT_SET[slot];
    int q = slot - CHb[s];
    int NT = NT16[s];
    int t0 = (NT*q)/CHn[s], t1 = (NT*(q+1))/CHn[s];
    int l = Ls[s], ww = WWs[s];
    const float* wp = (s==0)?w0:(s==1)?w1:(s==2)?w2:w3;
    const float* pp = (s==0)?p0:(s==1)?p1:(s==2)?p2:p3;

    extern __shared__ float sm[];
    float* sx = sm;
    float* sw = sm + SWOFF;
    unsigned* sden = (unsigned*)(sm + SRED_OFF);
    unsigned* spb  = sden + 40;

    int tid = threadIdx.x, bs = blockDim.x;
    // x: two copies (copy1 shifted by one element), rows padded with zeros
    const float* gx = g_xn + b*NC*GXROW;
    for (int i = tid; i < NC*GXROW; i += bs) {
        int cc = i / GXROW, o = i - cc*GXROW;
        float v = gx[i];
        sx[cc*SXSTR + o] = v;
        if (o > 0) sx[SX1OFF + cc*SXSTR + (o-1)] = v;
    }
    // negated w rows
    int wtot = NSH*NC*l;
    for (int i = tid; i < wtot; i += bs) {
        int rr = i / l, j = i - rr*l;
        sw[rr*ww + j] = -wp[i];
    }
    if (tid < 40) { sden[tid] = 0xFFFFFFFFu; spb[tid] = 0u; }
    __syncthreads();

    switch (s) {
        case 0: proc< 52, 461,  66>(sx, sw, pp, sden, spb, t0, t1, tid, bs); break;
        case 1: proc<103, 410, 130>(sx, sw, pp, sden, spb, t0, t1, tid, bs); break;
        case 2: proc<154, 359, 162>(sx, sw, pp, sden, spb, t0, t1, tid, bs); break;
        default: proc<256, 257, 258>(sx, sw, pp, sden, spb, t0, t1, tid, bs); break;
    }
    __syncthreads();
    if (tid < 40) {
        int idx = b*NCOL + s*40 + tid;
        atomicMin(&g_denc[idx], sden[tid]);
        atomicMax(&g_pbits[idx], spb[tid]);
    }
}

// ---------------- decode + matmul + losses ----------------
__global__ void k_final(float* __restrict__ out, const float* __restrict__ Wout,
                        const float* __restrict__ w0, const float* __restrict__ w1,
                        const float* __restrict__ w2, const float* __restrict__ w3) {
    int tid = threadIdx.x;   // 512
    if (blockIdx.x == 0) {
        for (int i = tid; i < NB*NCOL; i += 512) {
            out[OFF_DIST + i] = fdec(g_denc[i]);
            out[OFF_PROB + i] = __uint_as_float(g_pbits[i]);
        }
        __syncthreads();
        if (tid < NB*NOUT) {
            int bb = tid / NOUT, o = tid - bb*NOUT;
            const float* prw = out + OFF_PROB + bb*NCOL;
            const float* wr = Wout + o*NCOL;
            float sacc = 0.f;
#pragma unroll 8
            for (int j = 0; j < NCOL; j++) sacc += prw[j]*wr[j];
            out[bb*NOUT + o] = sacc;
        }
    } else {
        float reg = 0.f;
        for (int i = tid; i < NOUT*NCOL; i += 512) reg += fabsf(Wout[i]);
        const int Ls[4] = {52, 103, 154, 256};
        const float* wps[4] = {w0, w1, w2, w3};
        float div = 0.f;
        for (int t = tid; t < 800; t += 512) {
            int s = t / 200; int r = t % 200;
            int c = r / 25; int ij = r % 25; int i = ij / 5, j = ij % 5;
            if (i == j) continue;
            int l = Ls[s];
            const float* wa = wps[s] + (i*8 + c)*l;
            const float* wb = wps[s] + (j*8 + c)*l;
            float ss = 0.f;
            for (int kk = 0; kk < l; kk++) { float d = wa[kk]-wb[kk]+1e-6f; ss += d*d; }
            div += expf(-sqrtf(ss)) * (1.f/200.f);
        }
        __shared__ float r1[512], r2[512];
        r1[tid] = reg; r2[tid] = div;
        __syncthreads();
        for (int off = 256; off; off >>= 1) {
            if (tid < off) { r1[tid] += r1[tid+off]; r2[tid] += r2[tid+off]; }
            __syncthreads();
        }
        if (tid == 0) out[OFF_LOSS] = 0.1f*(r1[0]/1600.f) + 0.1f*r2[0];
    }
}

// ---------------- launch ----------------
extern "C" void kernel_launch(void* const* d_in, const int* in_sizes, int n_in,
                              void* d_out, int out_size) {
    const float* x = nullptr;
    const float* w[4] = {nullptr,nullptr,nullptr,nullptr};
    const float* pcm[4] = {nullptr,nullptr,nullptr,nullptr};
    const float* Wout = nullptr;
    for (int i = 0; i < n_in; i++) {
        switch (in_sizes[i]) {
            case 131072: x = (const float*)d_in[i]; break;
            case 2080:  w[0] = (const float*)d_in[i]; break;
            case 4120:  w[1] = (const float*)d_in[i]; break;
            case 6160:  w[2] = (const float*)d_in[i]; break;
            case 10240: w[3] = (const float*)d_in[i]; break;
            case 3688:  pcm[0] = (const float*)d_in[i]; break;
            case 3280:  pcm[1] = (const float*)d_in[i]; break;
            case 2872:  pcm[2] = (const float*)d_in[i]; break;
            case 2056:  pcm[3] = (const float*)d_in[i]; break;
            case 1600:  Wout = (const float*)d_in[i]; break;
            default: break;
        }
    }
    float* out = (float*)d_out;

    cudaFuncSetAttribute(k_main, cudaFuncAttributeMaxDynamicSharedMemorySize, SM_BYTES);

    k_norm<<<NB*NC, 128>>>(x);
    k_main<<<NB*14, 256, SM_BYTES>>>(w[0], w[1], w[2], w[3],
                                     pcm[0], pcm[1], pcm[2], pcm[3]);
    k_final<<<2, 512>>>(out, Wout, w[0], w[1], w[2], w[3]);
    (void)out_size;
}